// round 12
// baseline (speedup 1.0000x reference)
#include <cuda_runtime.h>
#include <cstdint>

#define B_  2
#define L_  2048
#define DM  1024
#define NH  16
#define DQ  64

// Scratch (allocation-free rule: __device__ globals)
__device__ float g_q[(size_t)B_ * NH * L_ * DQ];   // pre-scaled by 0.125
__device__ float g_k[(size_t)B_ * NH * L_ * DQ];
__device__ float g_v[(size_t)B_ * NH * L_ * DQ];
__device__ float g_o[(size_t)B_ * NH * L_ * DQ];
__device__ float g_y[(size_t)B_ * L_ * DM];
__device__ __align__(16) uint8_t g_mflag[B_ * 16 * 32]; // per (b, qblock128, ktile64)

__device__ __forceinline__ float to_tf32(float x) {
    asm("cvt.rna.tf32.f32 %0, %0;" : "+f"(x));
    return x;
}

__device__ __forceinline__ void mma8(float c[4], const uint32_t a[4], const uint32_t b[2]) {
    asm volatile(
        "mma.sync.aligned.m16n8k8.row.col.f32.tf32.tf32.f32 "
        "{%0,%1,%2,%3},{%4,%5,%6,%7},{%8,%9},{%0,%1,%2,%3};"
        : "+f"(c[0]), "+f"(c[1]), "+f"(c[2]), "+f"(c[3])
        : "r"(a[0]), "r"(a[1]), "r"(a[2]), "r"(a[3]), "r"(b[0]), "r"(b[1]));
}

// ldmatrix x4: four 8x8 b16 tiles == tf32 m16k8 A-fragment (or 2x n8 B-frags)
__device__ __forceinline__ void ldsm4(uint32_t& r0, uint32_t& r1,
                                      uint32_t& r2, uint32_t& r3, uint32_t addr) {
    asm volatile("ldmatrix.sync.aligned.m8n8.x4.shared.b16 {%0,%1,%2,%3}, [%4];"
                 : "=r"(r0), "=r"(r1), "=r"(r2), "=r"(r3) : "r"(addr));
}

// ---------------------------------------------------------------------------
// Prep: mask any-reduction per (b, 128-row block, 64-col tile). grid 1024
// ---------------------------------------------------------------------------
__global__ __launch_bounds__(256) void mask_reduce_kernel(const uint8_t* __restrict__ mask)
{
    int idx = blockIdx.x;
    int b = idx >> 9, qb = (idx >> 5) & 15, kt = idx & 31;
    int t = threadIdx.x;
    const uint8_t* p = mask + (size_t)b * L_ * L_ +
                       (size_t)(qb * 128 + (t >> 1)) * L_ + kt * 64 + (t & 1) * 32;
    uint4 a = *(const uint4*)p;
    uint4 c = *(const uint4*)(p + 16);
    unsigned any = a.x | a.y | a.z | a.w | c.x | c.y | c.z | c.w;
    int flag = __syncthreads_or((int)(any != 0));
    if (t == 0) g_mflag[idx] = (uint8_t)(flag ? 1 : 0);
}

// ---------------------------------------------------------------------------
// Kernel 1: fused QKV projection with tf32 MMA + ldmatrix fragment loads.
// Per (z, h): GEMM M=4096, N=64, K=1024. Block tile 128x64, BK=32.
// 8 warps in 4(m) x 2(n); warp tile 32x32. Q epilogue folds 0.125.
// ---------------------------------------------------------------------------
__global__ __launch_bounds__(256) void qkv_kernel(
    const float* __restrict__ X,
    const float* __restrict__ Wq,
    const float* __restrict__ Wk,
    const float* __restrict__ Wv)
{
    __shared__ float As[128 * 36];
    __shared__ float Bs[64 * 36];

    const float* W;
    float* O;
    if (blockIdx.z == 0)      { W = Wq; O = g_q; }
    else if (blockIdx.z == 1) { W = Wk; O = g_k; }
    else                      { W = Wv; O = g_v; }

    const int h  = blockIdx.y;
    const int m0 = blockIdx.x * 128;
    const int tid  = threadIdx.x;
    const int lane = tid & 31;
    const int warp = tid >> 5;
    const int r4 = lane >> 2;
    const int gg = lane & 3;
    const int wm = warp & 3;
    const int wn = warp >> 2;

    // ldmatrix per-thread addressing: row = lane&15, col half = lane>>4 (16B)
    const int lrow = lane & 15;
    const int lcol = (lane >> 4) << 4;   // byte offset
    const uint32_t uAs = (uint32_t)__cvta_generic_to_shared(As);
    const uint32_t uBs = (uint32_t)__cvta_generic_to_shared(Bs);

    const float* Wh = W + (size_t)h * DM * DQ;

    float acc[2][4][4];
#pragma unroll
    for (int i = 0; i < 2; i++)
#pragma unroll
        for (int j = 0; j < 4; j++)
#pragma unroll
            for (int t = 0; t < 4; t++) acc[i][j][t] = 0.f;

    const int eB  = tid & 63;
    const int kq0 = tid >> 6;

    for (int k0 = 0; k0 < DM; k0 += 32) {
#pragma unroll
        for (int i = 0; i < 4; i++) {
            int f = tid + 256 * i;
            int m = f >> 3, kq = f & 7;
            float4 v = *(const float4*)(X + (size_t)(m0 + m) * DM + k0 + 4 * kq);
            v.x = to_tf32(v.x); v.y = to_tf32(v.y);
            v.z = to_tf32(v.z); v.w = to_tf32(v.w);
            *(float4*)&As[m * 36 + 4 * kq] = v;
        }
#pragma unroll
        for (int p = 0; p < 2; p++) {
            int kq = kq0 + 4 * p;
            const float* src = Wh + (size_t)(k0 + 4 * kq) * DQ + eB;
            float4 v;
            v.x = to_tf32(src[0]);
            v.y = to_tf32(src[DQ]);
            v.z = to_tf32(src[2 * DQ]);
            v.w = to_tf32(src[3 * DQ]);
            *(float4*)&Bs[eB * 36 + 4 * kq] = v;
        }
        __syncthreads();

#pragma unroll
        for (int ks = 0; ks < 4; ks++) {
            const int cbyte = (ks << 5) + lcol;   // 8*ks floats + 16B half
            uint32_t a[2][4];
#pragma unroll
            for (int i = 0; i < 2; i++)
                ldsm4(a[i][0], a[i][1], a[i][2], a[i][3],
                      uAs + ((32 * wm + 16 * i + lrow) * 36) * 4 + cbyte);
#pragma unroll
            for (int jj = 0; jj < 2; jj++) {
                uint32_t m0r, m1r, m2r, m3r;
                ldsm4(m0r, m1r, m2r, m3r,
                      uBs + ((32 * wn + 16 * jj + lrow) * 36) * 4 + cbyte);
                uint32_t blo[2] = {m0r, m2r};
                uint32_t bhi[2] = {m1r, m3r};
#pragma unroll
                for (int i = 0; i < 2; i++) {
                    mma8(acc[i][2 * jj],     a[i], blo);
                    mma8(acc[i][2 * jj + 1], a[i], bhi);
                }
            }
        }
        __syncthreads();
    }

    const float s = (blockIdx.z == 0) ? 0.125f : 1.f;  // fold 1/sqrt(dqkv) into Q
#pragma unroll
    for (int i = 0; i < 2; i++) {
        int row = m0 + 32 * wm + 16 * i + r4;
        int b_  = row >> 11;
        int l   = row & (L_ - 1);
        float* base = O + ((((size_t)b_ * NH + h) * L_ + l) << 6);
#pragma unroll
        for (int j = 0; j < 4; j++) {
            int col = 32 * wn + 8 * j + 2 * gg;
            *(float2*)(base + col) = make_float2(acc[i][j][0] * s, acc[i][j][1] * s);
            *(float2*)(base + (8 << 6) + col) = make_float2(acc[i][j][2] * s, acc[i][j][3] * s);
        }
    }
}

// ---------------------------------------------------------------------------
// Kernel 2: flash attention, tf32 MMA + ldmatrix fragment loads.
// CTA = 128 query rows, 4 warps x 32 rows. Key tiles of 64. P through smem.
// Dynamic smem: Qs[128][68] | Ks[64][68] | Vs[64][68] | Ps[128][68] = 104448
// ---------------------------------------------------------------------------
__global__ __launch_bounds__(128) void attn_kernel(const uint8_t* __restrict__ mask)
{
    extern __shared__ float sm[];
    float* Qs = sm;                    // [128][68]
    float* Ks = Qs + 128 * 68;         // [64][68]
    float* Vs = Ks + 64 * 68;          // [64][68] ([e][l] layout)
    float* Ps = Vs + 64 * 68;          // [128][68]

    const int tid  = threadIdx.x;
    const int lane = tid & 31;
    const int warp = tid >> 5;
    const int r4 = lane >> 2;
    const int gg = lane & 3;
    const int h  = blockIdx.y;
    const int bb = blockIdx.z;
    const int m0 = blockIdx.x * 128;
    const size_t bh = (size_t)bb * NH + h;

    const int lrow = lane & 15;
    const int lcol = (lane >> 4) << 4;
    const uint32_t uQs = (uint32_t)__cvta_generic_to_shared(Qs);
    const uint32_t uKs = (uint32_t)__cvta_generic_to_shared(Ks);
    const uint32_t uVs = (uint32_t)__cvta_generic_to_shared(Vs);
    const uint32_t uPs = (uint32_t)__cvta_generic_to_shared(Ps);

    const float* Qg = g_q + ((bh * L_ + m0) << 6);
    const float* Kg = g_k + ((bh * L_) << 6);
    const float* Vg = g_v + ((bh * L_) << 6);
    const uint8_t* Mg = mask + ((size_t)bb * L_ + m0) * L_;

    // per-tile mask flags (32 bytes)
    const uint8_t* fl = g_mflag + (bb * 16 + blockIdx.x) * 32;
    uint4 f0 = *(const uint4*)fl;
    uint4 f1 = *(const uint4*)(fl + 16);
    unsigned fw[8] = {f0.x, f0.y, f0.z, f0.w, f1.x, f1.y, f1.z, f1.w};

    // Stage Q (tf32; already pre-scaled by 0.125)
#pragma unroll
    for (int i = 0; i < 16; i++) {
        int f = tid + 128 * i;
        int row = f >> 4, eq = f & 15;
        float4 v = *(const float4*)(Qg + ((size_t)row << 6) + 4 * eq);
        v.x = to_tf32(v.x); v.y = to_tf32(v.y);
        v.z = to_tf32(v.z); v.w = to_tf32(v.w);
        *(float4*)&Qs[row * 68 + 4 * eq] = v;
    }

    const int wq = warp * 32;          // 32 rows per warp
    float cO[2][8][4];
#pragma unroll
    for (int i = 0; i < 2; i++)
#pragma unroll
        for (int j = 0; j < 8; j++)
#pragma unroll
            for (int t = 0; t < 4; t++) cO[i][j][t] = 0.f;
    float mrow[2][2] = {{-1e30f, -1e30f}, {-1e30f, -1e30f}};
    float lrow2[2][2] = {{0.f, 0.f}, {0.f, 0.f}};

    const int eV  = tid & 63;
    const int kqV = tid >> 6;          // 0..1

    for (int kb = 0; kb < L_; kb += 64) {
        __syncthreads();
        // K tile (64 x 64)
#pragma unroll
        for (int i = 0; i < 8; i++) {
            int f = tid + 128 * i;
            int row = f >> 4, eq = f & 15;
            float4 v = *(const float4*)(Kg + ((size_t)(kb + row) << 6) + 4 * eq);
            v.x = to_tf32(v.x); v.y = to_tf32(v.y);
            v.z = to_tf32(v.z); v.w = to_tf32(v.w);
            *(float4*)&Ks[row * 68 + 4 * eq] = v;
        }
        // V^T tile ([e][l])
#pragma unroll
        for (int p = 0; p < 8; p++) {
            int kq = kqV + 2 * p;
            const float* src = Vg + ((size_t)(kb + 4 * kq) << 6) + eV;
            float4 v;
            v.x = to_tf32(src[0]);
            v.y = to_tf32(src[64]);
            v.z = to_tf32(src[128]);
            v.w = to_tf32(src[192]);
            *(float4*)&Vs[eV * 68 + 4 * kq] = v;
        }
        __syncthreads();

        const int t = kb >> 6;

        // S = Q K^T  (two m16 fragments per warp)
        float cS[2][8][4];
#pragma unroll
        for (int i = 0; i < 2; i++)
#pragma unroll
            for (int j = 0; j < 8; j++)
#pragma unroll
                for (int tt = 0; tt < 4; tt++) cS[i][j][tt] = 0.f;

#pragma unroll
        for (int ks = 0; ks < 8; ks++) {
            const int cbyte = (ks << 5) + lcol;
            uint32_t a[2][4];
#pragma unroll
            for (int i = 0; i < 2; i++)
                ldsm4(a[i][0], a[i][1], a[i][2], a[i][3],
                      uQs + ((wq + 16 * i + lrow) * 68) * 4 + cbyte);
#pragma unroll
            for (int jj = 0; jj < 4; jj++) {
                uint32_t m0r, m1r, m2r, m3r;
                ldsm4(m0r, m1r, m2r, m3r,
                      uKs + ((16 * jj + lrow) * 68) * 4 + cbyte);
                uint32_t blo[2] = {m0r, m2r};
                uint32_t bhi[2] = {m1r, m3r};
#pragma unroll
                for (int i = 0; i < 2; i++) {
                    mma8(cS[i][2 * jj],     a[i], blo);
                    mma8(cS[i][2 * jj + 1], a[i], bhi);
                }
            }
        }

        // mask (rare path; flag precomputed)
        if ((fw[t >> 2] >> ((t & 3) * 8)) & 0xff) {
#pragma unroll
            for (int i = 0; i < 2; i++)
#pragma unroll
                for (int j = 0; j < 8; j++) {
                    int col = kb + 8 * j + 2 * gg;
                    const uint8_t* mlo = Mg + (size_t)(wq + 16 * i + r4) * L_ + col;
                    const uint8_t* mhi = Mg + (size_t)(wq + 16 * i + r4 + 8) * L_ + col;
                    if (mlo[0]) cS[i][j][0] = -1e9f;
                    if (mlo[1]) cS[i][j][1] = -1e9f;
                    if (mhi[0]) cS[i][j][2] = -1e9f;
                    if (mhi[1]) cS[i][j][3] = -1e9f;
                }
        }

        // online softmax per (fragment, row-half)
#pragma unroll
        for (int i = 0; i < 2; i++)
#pragma unroll
            for (int hh = 0; hh < 2; hh++) {
                float mx = -1e30f;
#pragma unroll
                for (int j = 0; j < 8; j++)
                    mx = fmaxf(mx, fmaxf(cS[i][j][2 * hh], cS[i][j][2 * hh + 1]));
                mx = fmaxf(mx, __shfl_xor_sync(0xffffffffu, mx, 1));
                mx = fmaxf(mx, __shfl_xor_sync(0xffffffffu, mx, 2));
                float newm = fmaxf(mrow[i][hh], mx);
                float corr = __expf(mrow[i][hh] - newm);
                mrow[i][hh] = newm;
                float sum = 0.f;
#pragma unroll
                for (int j = 0; j < 8; j++) {
                    float p0 = __expf(cS[i][j][2 * hh] - newm);
                    float p1 = __expf(cS[i][j][2 * hh + 1] - newm);
                    cS[i][j][2 * hh] = p0;
                    cS[i][j][2 * hh + 1] = p1;
                    sum += p0 + p1;
                }
                sum += __shfl_xor_sync(0xffffffffu, sum, 1);
                sum += __shfl_xor_sync(0xffffffffu, sum, 2);
                lrow2[i][hh] = lrow2[i][hh] * corr + sum;
#pragma unroll
                for (int j = 0; j < 8; j++) {
                    cO[i][j][2 * hh] *= corr;
                    cO[i][j][2 * hh + 1] *= corr;
                }
            }

        // store P (tf32) to this warp's rows of Ps
#pragma unroll
        for (int i = 0; i < 2; i++)
#pragma unroll
            for (int j = 0; j < 8; j++) {
                int row = wq + 16 * i + r4;
                *(float2*)&Ps[row * 68 + 8 * j + 2 * gg] =
                    make_float2(to_tf32(cS[i][j][0]), to_tf32(cS[i][j][1]));
                *(float2*)&Ps[(row + 8) * 68 + 8 * j + 2 * gg] =
                    make_float2(to_tf32(cS[i][j][2]), to_tf32(cS[i][j][3]));
            }
        __syncwarp();

        // O += P V
#pragma unroll
        for (int ks = 0; ks < 8; ks++) {
            const int cbyte = (ks << 5) + lcol;
            uint32_t a[2][4];
#pragma unroll
            for (int i = 0; i < 2; i++)
                ldsm4(a[i][0], a[i][1], a[i][2], a[i][3],
                      uPs + ((wq + 16 * i + lrow) * 68) * 4 + cbyte);
#pragma unroll
            for (int jj = 0; jj < 4; jj++) {
                uint32_t m0r, m1r, m2r, m3r;
                ldsm4(m0r, m1r, m2r, m3r,
                      uVs + ((16 * jj + lrow) * 68) * 4 + cbyte);
                uint32_t blo[2] = {m0r, m2r};
                uint32_t bhi[2] = {m1r, m3r};
#pragma unroll
                for (int i = 0; i < 2; i++) {
                    mma8(cO[i][2 * jj],     a[i], blo);
                    mma8(cO[i][2 * jj + 1], a[i], bhi);
                }
            }
        }
    }

    // epilogue
#pragma unroll
    for (int i = 0; i < 2; i++) {
        float inv0 = 1.f / lrow2[i][0];
        float inv1 = 1.f / lrow2[i][1];
        float* Ob = g_o + ((bh * L_ + m0 + wq + 16 * i) << 6);
#pragma unroll
        for (int j = 0; j < 8; j++) {
            int col = 8 * j + 2 * gg;
            *(float2*)(Ob + ((size_t)r4 << 6) + col) =
                make_float2(cO[i][j][0] * inv0, cO[i][j][1] * inv0);
            *(float2*)(Ob + ((size_t)(r4 + 8) << 6) + col) =
                make_float2(cO[i][j][2] * inv1, cO[i][j][3] * inv1);
        }
    }
}

// ---------------------------------------------------------------------------
// Kernel 3: output projection + residual, tf32 MMA + ldmatrix fragment loads.
// GEMM M=4096, N=1024, K=1024. Block tile 128x64, BK=32.
// ---------------------------------------------------------------------------
__global__ __launch_bounds__(256) void oproj_kernel(
    const float* __restrict__ X, const float* __restrict__ Wo)
{
    __shared__ float As[128 * 36];
    __shared__ float Bs[64 * 36];

    const int m0 = blockIdx.x * 128;
    const int n0 = blockIdx.y * 64;
    const int tid  = threadIdx.x;
    const int lane = tid & 31;
    const int warp = tid >> 5;
    const int r4 = lane >> 2;
    const int gg = lane & 3;
    const int wm = warp & 3;
    const int wn = warp >> 2;

    const int lrow = lane & 15;
    const int lcol = (lane >> 4) << 4;
    const uint32_t uAs = (uint32_t)__cvta_generic_to_shared(As);
    const uint32_t uBs = (uint32_t)__cvta_generic_to_shared(Bs);

    float acc[2][4][4];
#pragma unroll
    for (int i = 0; i < 2; i++)
#pragma unroll
        for (int j = 0; j < 4; j++)
#pragma unroll
            for (int t = 0; t < 4; t++) acc[i][j][t] = 0.f;

    const int eB  = tid & 63;
    const int kq0 = tid >> 6;

    for (int k0 = 0; k0 < DM; k0 += 32) {
#pragma unroll
        for (int i = 0; i < 4; i++) {
            int f = tid + 256 * i;
            int m = f >> 3, kq = f & 7;
            int row = m0 + m;
            int b_ = row >> 11, l = row & (L_ - 1);
            int k  = k0 + 4 * kq;
            int hk = k >> 6, ek = k & 63;
            float4 v = *(const float4*)(
                g_o + ((((size_t)b_ * NH + hk) * L_ + l) << 6) + ek);
            v.x = to_tf32(v.x); v.y = to_tf32(v.y);
            v.z = to_tf32(v.z); v.w = to_tf32(v.w);
            *(float4*)&As[m * 36 + 4 * kq] = v;
        }
#pragma unroll
        for (int p = 0; p < 2; p++) {
            int kq = kq0 + 4 * p;
            const float* src = Wo + (size_t)(k0 + 4 * kq) * DM + n0 + eB;
            float4 v;
            v.x = to_tf32(src[0]);
            v.y = to_tf32(src[DM]);
            v.z = to_tf32(src[2 * DM]);
            v.w = to_tf32(src[3 * DM]);
            *(float4*)&Bs[eB * 36 + 4 * kq] = v;
        }
        __syncthreads();

#pragma unroll
        for (int ks = 0; ks < 4; ks++) {
            const int cbyte = (ks << 5) + lcol;
            uint32_t a[2][4];
#pragma unroll
            for (int i = 0; i < 2; i++)
                ldsm4(a[i][0], a[i][1], a[i][2], a[i][3],
                      uAs + ((32 * wm + 16 * i + lrow) * 36) * 4 + cbyte);
#pragma unroll
            for (int jj = 0; jj < 2; jj++) {
                uint32_t m0r, m1r, m2r, m3r;
                ldsm4(m0r, m1r, m2r, m3r,
                      uBs + ((32 * wn + 16 * jj + lrow) * 36) * 4 + cbyte);
                uint32_t blo[2] = {m0r, m2r};
                uint32_t bhi[2] = {m1r, m3r};
#pragma unroll
                for (int i = 0; i < 2; i++) {
                    mma8(acc[i][2 * jj],     a[i], blo);
                    mma8(acc[i][2 * jj + 1], a[i], bhi);
                }
            }
        }
        __syncthreads();
    }

#pragma unroll
    for (int i = 0; i < 2; i++) {
        int row = m0 + 32 * wm + 16 * i + r4;
#pragma unroll
        for (int j = 0; j < 4; j++) {
            int col = n0 + 32 * wn + 8 * j + 2 * gg;
            float2 x0 = *(const float2*)(X + (size_t)row * DM + col);
            float2 x1 = *(const float2*)(X + (size_t)(row + 8) * DM + col);
            *(float2*)(g_y + (size_t)row * DM + col) =
                make_float2(acc[i][j][0] + x0.x, acc[i][j][1] + x0.y);
            *(float2*)(g_y + (size_t)(row + 8) * DM + col) =
                make_float2(acc[i][j][2] + x1.x, acc[i][j][3] + x1.y);
        }
    }
}

// ---------------------------------------------------------------------------
// Kernel 4: LayerNorm, one block (256 threads) per row of 1024.
// ---------------------------------------------------------------------------
__global__ __launch_bounds__(256) void ln_kernel(
    const float* __restrict__ gamma, const float* __restrict__ beta,
    float* __restrict__ out)
{
    const int row = blockIdx.x;
    const int tid = threadIdx.x;
    const float* Y = g_y + (size_t)row * DM;

    float4 v = *(const float4*)(Y + (tid << 2));
    float s  = v.x + v.y + v.z + v.w;
    float sq = v.x * v.x + v.y * v.y + v.z * v.z + v.w * v.w;

#pragma unroll
    for (int off = 16; off > 0; off >>= 1) {
        s  += __shfl_xor_sync(0xffffffffu, s, off);
        sq += __shfl_xor_sync(0xffffffffu, sq, off);
    }

    __shared__ float red[18];
    const int wid = tid >> 5;
    if ((tid & 31) == 0) { red[wid] = s; red[wid + 8] = sq; }
    __syncthreads();
    if (tid == 0) {
        float ts = 0.f, tq = 0.f;
#pragma unroll
        for (int w = 0; w < 8; w++) { ts += red[w]; tq += red[w + 8]; }
        float mu  = ts * (1.f / DM);
        float var = tq * (1.f / DM) - mu * mu;
        red[16] = mu;
        red[17] = rsqrtf(var + 1e-5f);
    }
    __syncthreads();
    float mu   = red[16];
    float rstd = red[17];

    float4 g = *(const float4*)(gamma + (tid << 2));
    float4 b = *(const float4*)(beta  + (tid << 2));
    float4 res;
    res.x = (v.x - mu) * rstd * g.x + b.x;
    res.y = (v.y - mu) * rstd * g.y + b.y;
    res.z = (v.z - mu) * rstd * g.z + b.z;
    res.w = (v.w - mu) * rstd * g.w + b.w;
    *(float4*)(out + (size_t)row * DM + (tid << 2)) = res;
}

// ---------------------------------------------------------------------------
// Launch
// ---------------------------------------------------------------------------
extern "C" void kernel_launch(void* const* d_in, const int* in_sizes, int n_in,
                              void* d_out, int out_size)
{
    const float*   x     = (const float*)d_in[0];
    const uint8_t* mask  = (const uint8_t*)d_in[1];
    const float*   wq    = (const float*)d_in[2];
    const float*   wk    = (const float*)d_in[3];
    const float*   wv    = (const float*)d_in[4];
    const float*   wo    = (const float*)d_in[5];
    const float*   gamma = (const float*)d_in[6];
    const float*   beta  = (const float*)d_in[7];
    float*         out   = (float*)d_out;

    const int attn_smem = (128 * 68 + 64 * 68 + 64 * 68 + 128 * 68) * 4; // 104448
    cudaFuncSetAttribute(attn_kernel,
                         cudaFuncAttributeMaxDynamicSharedMemorySize, attn_smem);

    mask_reduce_kernel<<<B_ * 16 * 32, 256>>>(mask);

    dim3 g1((B_ * L_) / 128, NH, 3);
    qkv_kernel<<<g1, 256>>>(x, wq, wk, wv);

    dim3 g2(L_ / 128, NH, B_);
    attn_kernel<<<g2, 128, attn_smem>>>(mask);

    dim3 g3((B_ * L_) / 128, DM / 64);
    oproj_kernel<<<g3, 256>>>(x, wo);

    ln_kernel<<<B_ * L_, 256>>>(gamma, beta, out);
}

// round 13
// speedup vs baseline: 1.6017x; 1.6017x over previous
#include <cuda_runtime.h>
#include <cuda_fp16.h>
#include <cstdint>

#define B_  2
#define L_  2048
#define DM  1024
#define NH  16
#define DQ  64

// Scratch (allocation-free rule: __device__ globals) — intermediates in fp16
__device__ __half g_q[(size_t)B_ * NH * L_ * DQ];   // pre-scaled by 0.125
__device__ __half g_k[(size_t)B_ * NH * L_ * DQ];
__device__ __half g_v[(size_t)B_ * NH * L_ * DQ];
__device__ __half g_o[(size_t)B_ * NH * L_ * DQ];
__device__ float  g_y[(size_t)B_ * L_ * DM];
__device__ __align__(16) uint8_t g_mflag[B_ * 16 * 32]; // per (b, qblock128, ktile64)

__device__ __forceinline__ void mma16(float c[4], const uint32_t a[4], const uint32_t b[2]) {
    asm volatile(
        "mma.sync.aligned.m16n8k16.row.col.f32.f16.f16.f32 "
        "{%0,%1,%2,%3},{%4,%5,%6,%7},{%8,%9},{%0,%1,%2,%3};"
        : "+f"(c[0]), "+f"(c[1]), "+f"(c[2]), "+f"(c[3])
        : "r"(a[0]), "r"(a[1]), "r"(a[2]), "r"(a[3]), "r"(b[0]), "r"(b[1]));
}

__device__ __forceinline__ void ldsm4(uint32_t& r0, uint32_t& r1,
                                      uint32_t& r2, uint32_t& r3, uint32_t addr) {
    asm volatile("ldmatrix.sync.aligned.m8n8.x4.shared.b16 {%0,%1,%2,%3}, [%4];"
                 : "=r"(r0), "=r"(r1), "=r"(r2), "=r"(r3) : "r"(addr));
}
__device__ __forceinline__ void ldsm4t(uint32_t& r0, uint32_t& r1,
                                       uint32_t& r2, uint32_t& r3, uint32_t addr) {
    asm volatile("ldmatrix.sync.aligned.m8n8.x4.trans.shared.b16 {%0,%1,%2,%3}, [%4];"
                 : "=r"(r0), "=r"(r1), "=r"(r2), "=r"(r3) : "r"(addr));
}

__device__ __forceinline__ uint32_t pack_h2(float a, float b) {
    __half2 h = __floats2half2_rn(a, b);
    return *(uint32_t*)&h;
}

// ---------------------------------------------------------------------------
// Prep: mask any-reduction per (b, 128-row block, 64-col tile). grid 1024
// ---------------------------------------------------------------------------
__global__ __launch_bounds__(256) void mask_reduce_kernel(const uint8_t* __restrict__ mask)
{
    int idx = blockIdx.x;
    int b = idx >> 9, qb = (idx >> 5) & 15, kt = idx & 31;
    int t = threadIdx.x;
    const uint8_t* p = mask + (size_t)b * L_ * L_ +
                       (size_t)(qb * 128 + (t >> 1)) * L_ + kt * 64 + (t & 1) * 32;
    uint4 a = *(const uint4*)p;
    uint4 c = *(const uint4*)(p + 16);
    unsigned any = a.x | a.y | a.z | a.w | c.x | c.y | c.z | c.w;
    int flag = __syncthreads_or((int)(any != 0));
    if (t == 0) g_mflag[idx] = (uint8_t)(flag ? 1 : 0);
}

// ---------------------------------------------------------------------------
// Kernel 1: fused QKV projection, fp16 MMA (m16n8k16).
// Per (z,h): M=4096, N=64, K=1024. Block 128x64, BK=32. 8 warps (4m x 2n).
// Smem rows: 40 halves (80B) -> ldmatrix conflict-free.
// ---------------------------------------------------------------------------
__global__ __launch_bounds__(256) void qkv_kernel(
    const float* __restrict__ X,
    const float* __restrict__ Wq,
    const float* __restrict__ Wk,
    const float* __restrict__ Wv)
{
    __shared__ __half As[128 * 40];
    __shared__ __half Bs[64 * 40];

    const float* W;
    __half* O;
    if (blockIdx.z == 0)      { W = Wq; O = g_q; }
    else if (blockIdx.z == 1) { W = Wk; O = g_k; }
    else                      { W = Wv; O = g_v; }

    const int h  = blockIdx.y;
    const int m0 = blockIdx.x * 128;
    const int tid  = threadIdx.x;
    const int lane = tid & 31;
    const int warp = tid >> 5;
    const int r4 = lane >> 2;
    const int gg = lane & 3;
    const int wm = warp & 3;
    const int wn = warp >> 2;

    const int lrow = lane & 15;
    const int lcol = (lane >> 4) << 4;   // byte offset
    const uint32_t uAs = (uint32_t)__cvta_generic_to_shared(As);
    const uint32_t uBs = (uint32_t)__cvta_generic_to_shared(Bs);

    const float* Wh = W + (size_t)h * DM * DQ;

    float acc[2][4][4];
#pragma unroll
    for (int i = 0; i < 2; i++)
#pragma unroll
        for (int j = 0; j < 4; j++)
#pragma unroll
            for (int t = 0; t < 4; t++) acc[i][j][t] = 0.f;

    const int eB  = tid & 63;
    const int kq0 = tid >> 6;

    for (int k0 = 0; k0 < DM; k0 += 32) {
        // A tile 128x32: float4 loads, pack to half2 pairs
#pragma unroll
        for (int i = 0; i < 4; i++) {
            int f = tid + 256 * i;
            int m = f >> 3, kq = f & 7;
            float4 v = *(const float4*)(X + (size_t)(m0 + m) * DM + k0 + 4 * kq);
            uint2 u = make_uint2(pack_h2(v.x, v.y), pack_h2(v.z, v.w));
            *(uint2*)&As[m * 40 + 4 * kq] = u;
        }
        // B^T tile 64x32: strided gmem reads (k-consecutive), pack
#pragma unroll
        for (int p = 0; p < 2; p++) {
            int kq = kq0 + 4 * p;
            const float* src = Wh + (size_t)(k0 + 4 * kq) * DQ + eB;
            uint2 u = make_uint2(pack_h2(src[0], src[DQ]),
                                 pack_h2(src[2 * DQ], src[3 * DQ]));
            *(uint2*)&Bs[eB * 40 + 4 * kq] = u;
        }
        __syncthreads();

#pragma unroll
        for (int ks = 0; ks < 2; ks++) {           // two k16 steps
            const int cbyte = (ks << 5) + lcol;
            uint32_t a[2][4];
#pragma unroll
            for (int i = 0; i < 2; i++)
                ldsm4(a[i][0], a[i][1], a[i][2], a[i][3],
                      uAs + (32 * wm + 16 * i + lrow) * 80 + cbyte);
#pragma unroll
            for (int jj = 0; jj < 2; jj++) {
                uint32_t m0r, m1r, m2r, m3r;
                ldsm4(m0r, m1r, m2r, m3r,
                      uBs + (32 * wn + 16 * jj + lrow) * 80 + cbyte);
                uint32_t blo[2] = {m0r, m2r};
                uint32_t bhi[2] = {m1r, m3r};
#pragma unroll
                for (int i = 0; i < 2; i++) {
                    mma16(acc[i][2 * jj],     a[i], blo);
                    mma16(acc[i][2 * jj + 1], a[i], bhi);
                }
            }
        }
        __syncthreads();
    }

    const float s = (blockIdx.z == 0) ? 0.125f : 1.f;  // fold 1/sqrt(dqkv) into Q
#pragma unroll
    for (int i = 0; i < 2; i++) {
        int row = m0 + 32 * wm + 16 * i + r4;
        int b_  = row >> 11;
        int l   = row & (L_ - 1);
        __half* base = O + ((((size_t)b_ * NH + h) * L_ + l) << 6);
#pragma unroll
        for (int j = 0; j < 4; j++) {
            int col = 32 * wn + 8 * j + 2 * gg;
            *(uint32_t*)(base + col) = pack_h2(acc[i][j][0] * s, acc[i][j][1] * s);
            *(uint32_t*)(base + (8 << 6) + col) = pack_h2(acc[i][j][2] * s, acc[i][j][3] * s);
        }
    }
}

// ---------------------------------------------------------------------------
// Kernel 2: flash attention, fp16 MMA. CTA = 128 q-rows, 4 warps x 32 rows.
// K/V staged as pure 16B copies (already half). V row-major; PV uses
// ldmatrix.trans. Smem rows: 72 halves (144B).
// Dyn smem: Qs[128][72] Ks[64][72] Vs[64][72] Ps[128][72] = 55296 B
// ---------------------------------------------------------------------------
__global__ __launch_bounds__(128) void attn_kernel(const uint8_t* __restrict__ mask)
{
    extern __shared__ __half smh[];
    __half* Qs = smh;                  // [128][72]
    __half* Ks = Qs + 128 * 72;        // [64][72]
    __half* Vs = Ks + 64 * 72;         // [64][72]  row-major [key][e]
    __half* Ps = Vs + 64 * 72;         // [128][72]

    const int tid  = threadIdx.x;
    const int lane = tid & 31;
    const int warp = tid >> 5;
    const int r4 = lane >> 2;
    const int gg = lane & 3;
    const int h  = blockIdx.y;
    const int bb = blockIdx.z;
    const int m0 = blockIdx.x * 128;
    const size_t bh = (size_t)bb * NH + h;

    const int lrow = lane & 15;
    const int lcol = (lane >> 4) << 4;
    const uint32_t uQs = (uint32_t)__cvta_generic_to_shared(Qs);
    const uint32_t uKs = (uint32_t)__cvta_generic_to_shared(Ks);
    const uint32_t uVs = (uint32_t)__cvta_generic_to_shared(Vs);
    const uint32_t uPs = (uint32_t)__cvta_generic_to_shared(Ps);

    const __half* Qg = g_q + ((bh * L_ + m0) << 6);
    const __half* Kg = g_k + ((bh * L_) << 6);
    const __half* Vg = g_v + ((bh * L_) << 6);
    const uint8_t* Mg = mask + ((size_t)bb * L_ + m0) * L_;

    // per-tile mask flags (32 bytes)
    const uint8_t* fl = g_mflag + (bb * 16 + blockIdx.x) * 32;
    uint4 f0 = *(const uint4*)fl;
    uint4 f1 = *(const uint4*)(fl + 16);
    unsigned fw[8] = {f0.x, f0.y, f0.z, f0.w, f1.x, f1.y, f1.z, f1.w};

    // Stage Q: pure 16B copies (1024 chunks / 128 threads = 8)
#pragma unroll
    for (int i = 0; i < 8; i++) {
        int f = tid + 128 * i;
        int row = f >> 3, eq = f & 7;
        *(uint4*)&Qs[row * 72 + 8 * eq] = *(const uint4*)(Qg + ((size_t)row << 6) + 8 * eq);
    }

    const int wq = warp * 32;
    float cO[2][8][4];
#pragma unroll
    for (int i = 0; i < 2; i++)
#pragma unroll
        for (int j = 0; j < 8; j++)
#pragma unroll
            for (int t = 0; t < 4; t++) cO[i][j][t] = 0.f;
    float mrow[2][2] = {{-1e30f, -1e30f}, {-1e30f, -1e30f}};
    float lrow2[2][2] = {{0.f, 0.f}, {0.f, 0.f}};

    for (int kb = 0; kb < L_; kb += 64) {
        __syncthreads();
        // K, V tiles: 16B copies (512 chunks each / 128 threads = 4)
#pragma unroll
        for (int i = 0; i < 4; i++) {
            int f = tid + 128 * i;
            int row = f >> 3, eq = f & 7;
            *(uint4*)&Ks[row * 72 + 8 * eq] =
                *(const uint4*)(Kg + ((size_t)(kb + row) << 6) + 8 * eq);
        }
#pragma unroll
        for (int i = 0; i < 4; i++) {
            int f = tid + 128 * i;
            int row = f >> 3, eq = f & 7;
            *(uint4*)&Vs[row * 72 + 8 * eq] =
                *(const uint4*)(Vg + ((size_t)(kb + row) << 6) + 8 * eq);
        }
        __syncthreads();

        const int t = kb >> 6;

        // S = Q K^T : 4 k16 steps
        float cS[2][8][4];
#pragma unroll
        for (int i = 0; i < 2; i++)
#pragma unroll
            for (int j = 0; j < 8; j++)
#pragma unroll
                for (int tt = 0; tt < 4; tt++) cS[i][j][tt] = 0.f;

#pragma unroll
        for (int ks = 0; ks < 4; ks++) {
            const int cbyte = (ks << 5) + lcol;
            uint32_t a[2][4];
#pragma unroll
            for (int i = 0; i < 2; i++)
                ldsm4(a[i][0], a[i][1], a[i][2], a[i][3],
                      uQs + (wq + 16 * i + lrow) * 144 + cbyte);
#pragma unroll
            for (int jj = 0; jj < 4; jj++) {
                uint32_t m0r, m1r, m2r, m3r;
                ldsm4(m0r, m1r, m2r, m3r,
                      uKs + (16 * jj + lrow) * 144 + cbyte);
                uint32_t blo[2] = {m0r, m2r};
                uint32_t bhi[2] = {m1r, m3r};
#pragma unroll
                for (int i = 0; i < 2; i++) {
                    mma16(cS[i][2 * jj],     a[i], blo);
                    mma16(cS[i][2 * jj + 1], a[i], bhi);
                }
            }
        }

        // mask (rare path; flag precomputed)
        if ((fw[t >> 2] >> ((t & 3) * 8)) & 0xff) {
#pragma unroll
            for (int i = 0; i < 2; i++)
#pragma unroll
                for (int j = 0; j < 8; j++) {
                    int col = kb + 8 * j + 2 * gg;
                    const uint8_t* mlo = Mg + (size_t)(wq + 16 * i + r4) * L_ + col;
                    const uint8_t* mhi = Mg + (size_t)(wq + 16 * i + r4 + 8) * L_ + col;
                    if (mlo[0]) cS[i][j][0] = -1e9f;
                    if (mlo[1]) cS[i][j][1] = -1e9f;
                    if (mhi[0]) cS[i][j][2] = -1e9f;
                    if (mhi[1]) cS[i][j][3] = -1e9f;
                }
        }

        // online softmax per (fragment, row-half)
#pragma unroll
        for (int i = 0; i < 2; i++)
#pragma unroll
            for (int hh = 0; hh < 2; hh++) {
                float mx = -1e30f;
#pragma unroll
                for (int j = 0; j < 8; j++)
                    mx = fmaxf(mx, fmaxf(cS[i][j][2 * hh], cS[i][j][2 * hh + 1]));
                mx = fmaxf(mx, __shfl_xor_sync(0xffffffffu, mx, 1));
                mx = fmaxf(mx, __shfl_xor_sync(0xffffffffu, mx, 2));
                float newm = fmaxf(mrow[i][hh], mx);
                float corr = __expf(mrow[i][hh] - newm);
                mrow[i][hh] = newm;
                float sum = 0.f;
#pragma unroll
                for (int j = 0; j < 8; j++) {
                    float p0 = __expf(cS[i][j][2 * hh] - newm);
                    float p1 = __expf(cS[i][j][2 * hh + 1] - newm);
                    cS[i][j][2 * hh] = p0;
                    cS[i][j][2 * hh + 1] = p1;
                    sum += p0 + p1;
                }
                sum += __shfl_xor_sync(0xffffffffu, sum, 1);
                sum += __shfl_xor_sync(0xffffffffu, sum, 2);
                lrow2[i][hh] = lrow2[i][hh] * corr + sum;
#pragma unroll
                for (int j = 0; j < 8; j++) {
                    cO[i][j][2 * hh] *= corr;
                    cO[i][j][2 * hh + 1] *= corr;
                }
            }

        // store P (half) to this warp's rows of Ps
#pragma unroll
        for (int i = 0; i < 2; i++)
#pragma unroll
            for (int j = 0; j < 8; j++) {
                int row = wq + 16 * i + r4;
                *(uint32_t*)&Ps[row * 72 + 8 * j + 2 * gg] =
                    pack_h2(cS[i][j][0], cS[i][j][1]);
                *(uint32_t*)&Ps[(row + 8) * 72 + 8 * j + 2 * gg] =
                    pack_h2(cS[i][j][2], cS[i][j][3]);
            }
        __syncwarp();

        // O += P V : A from Ps, B from row-major Vs via ldmatrix.trans
#pragma unroll
        for (int ks = 0; ks < 4; ks++) {
            const int cbyte = (ks << 5) + lcol;
            uint32_t a[2][4];
#pragma unroll
            for (int i = 0; i < 2; i++)
                ldsm4(a[i][0], a[i][1], a[i][2], a[i][3],
                      uPs + (wq + 16 * i + lrow) * 144 + cbyte);
#pragma unroll
            for (int jj = 0; jj < 4; jj++) {
                uint32_t m0r, m1r, m2r, m3r;
                // rows = keys of this k-step; cols = e-groups 2jj, 2jj+1
                ldsm4t(m0r, m1r, m2r, m3r,
                       uVs + (16 * ks + lrow) * 144 + (jj << 5) + lcol);
                uint32_t blo[2] = {m0r, m1r};
                uint32_t bhi[2] = {m2r, m3r};
#pragma unroll
                for (int i = 0; i < 2; i++) {
                    mma16(cO[i][2 * jj],     a[i], blo);
                    mma16(cO[i][2 * jj + 1], a[i], bhi);
                }
            }
        }
    }

    // epilogue (half, feeds oproj A operand)
#pragma unroll
    for (int i = 0; i < 2; i++) {
        float inv0 = 1.f / lrow2[i][0];
        float inv1 = 1.f / lrow2[i][1];
        __half* Ob = g_o + ((bh * L_ + m0 + wq + 16 * i) << 6);
#pragma unroll
        for (int j = 0; j < 8; j++) {
            int col = 8 * j + 2 * gg;
            *(uint32_t*)(Ob + ((size_t)r4 << 6) + col) =
                pack_h2(cO[i][j][0] * inv0, cO[i][j][1] * inv0);
            *(uint32_t*)(Ob + ((size_t)(r4 + 8) << 6) + col) =
                pack_h2(cO[i][j][2] * inv1, cO[i][j][3] * inv1);
        }
    }
}

// ---------------------------------------------------------------------------
// Kernel 3: output projection + residual, fp16 MMA.
// GEMM M=4096, N=1024, K=1024. Block 128x64, BK=32.
// A tile: raw 16B copies from g_o (already half).
// ---------------------------------------------------------------------------
__global__ __launch_bounds__(256) void oproj_kernel(
    const float* __restrict__ X, const float* __restrict__ Wo)
{
    __shared__ __half As[128 * 40];
    __shared__ __half Bs[64 * 40];

    const int m0 = blockIdx.x * 128;
    const int n0 = blockIdx.y * 64;
    const int tid  = threadIdx.x;
    const int lane = tid & 31;
    const int warp = tid >> 5;
    const int r4 = lane >> 2;
    const int gg = lane & 3;
    const int wm = warp & 3;
    const int wn = warp >> 2;

    const int lrow = lane & 15;
    const int lcol = (lane >> 4) << 4;
    const uint32_t uAs = (uint32_t)__cvta_generic_to_shared(As);
    const uint32_t uBs = (uint32_t)__cvta_generic_to_shared(Bs);

    float acc[2][4][4];
#pragma unroll
    for (int i = 0; i < 2; i++)
#pragma unroll
        for (int j = 0; j < 4; j++)
#pragma unroll
            for (int t = 0; t < 4; t++) acc[i][j][t] = 0.f;

    const int eB  = tid & 63;
    const int kq0 = tid >> 6;

    for (int k0 = 0; k0 < DM; k0 += 32) {
        const int head  = k0 >> 6;
        const int ebase = k0 & 63;
        // A tile: 512 16B chunks / 256 threads = 2
#pragma unroll
        for (int i = 0; i < 2; i++) {
            int f = tid + 256 * i;
            int m = f >> 2, kq = f & 3;
            int row = m0 + m;
            int b_ = row >> 11, l = row & (L_ - 1);
            *(uint4*)&As[m * 40 + 8 * kq] = *(const uint4*)(
                g_o + ((((size_t)b_ * NH + head) * L_ + l) << 6) + ebase + 8 * kq);
        }
        // B^T tile: Wo fp32 strided -> half
#pragma unroll
        for (int p = 0; p < 2; p++) {
            int kq = kq0 + 4 * p;
            const float* src = Wo + (size_t)(k0 + 4 * kq) * DM + n0 + eB;
            uint2 u = make_uint2(pack_h2(src[0], src[DM]),
                                 pack_h2(src[2 * DM], src[3 * DM]));
            *(uint2*)&Bs[eB * 40 + 4 * kq] = u;
        }
        __syncthreads();

#pragma unroll
        for (int ks = 0; ks < 2; ks++) {
            const int cbyte = (ks << 5) + lcol;
            uint32_t a[2][4];
#pragma unroll
            for (int i = 0; i < 2; i++)
                ldsm4(a[i][0], a[i][1], a[i][2], a[i][3],
                      uAs + (32 * wm + 16 * i + lrow) * 80 + cbyte);
#pragma unroll
            for (int jj = 0; jj < 2; jj++) {
                uint32_t m0r, m1r, m2r, m3r;
                ldsm4(m0r, m1r, m2r, m3r,
                      uBs + (32 * wn + 16 * jj + lrow) * 80 + cbyte);
                uint32_t blo[2] = {m0r, m2r};
                uint32_t bhi[2] = {m1r, m3r};
#pragma unroll
                for (int i = 0; i < 2; i++) {
                    mma16(acc[i][2 * jj],     a[i], blo);
                    mma16(acc[i][2 * jj + 1], a[i], bhi);
                }
            }
        }
        __syncthreads();
    }

#pragma unroll
    for (int i = 0; i < 2; i++) {
        int row = m0 + 32 * wm + 16 * i + r4;
#pragma unroll
        for (int j = 0; j < 4; j++) {
            int col = n0 + 32 * wn + 8 * j + 2 * gg;
            float2 x0 = *(const float2*)(X + (size_t)row * DM + col);
            float2 x1 = *(const float2*)(X + (size_t)(row + 8) * DM + col);
            *(float2*)(g_y + (size_t)row * DM + col) =
                make_float2(acc[i][j][0] + x0.x, acc[i][j][1] + x0.y);
            *(float2*)(g_y + (size_t)(row + 8) * DM + col) =
                make_float2(acc[i][j][2] + x1.x, acc[i][j][3] + x1.y);
        }
    }
}

// ---------------------------------------------------------------------------
// Kernel 4: LayerNorm, one block (256 threads) per row of 1024.
// ---------------------------------------------------------------------------
__global__ __launch_bounds__(256) void ln_kernel(
    const float* __restrict__ gamma, const float* __restrict__ beta,
    float* __restrict__ out)
{
    const int row = blockIdx.x;
    const int tid = threadIdx.x;
    const float* Y = g_y + (size_t)row * DM;

    float4 v = *(const float4*)(Y + (tid << 2));
    float s  = v.x + v.y + v.z + v.w;
    float sq = v.x * v.x + v.y * v.y + v.z * v.z + v.w * v.w;

#pragma unroll
    for (int off = 16; off > 0; off >>= 1) {
        s  += __shfl_xor_sync(0xffffffffu, s, off);
        sq += __shfl_xor_sync(0xffffffffu, sq, off);
    }

    __shared__ float red[18];
    const int wid = tid >> 5;
    if ((tid & 31) == 0) { red[wid] = s; red[wid + 8] = sq; }
    __syncthreads();
    if (tid == 0) {
        float ts = 0.f, tq = 0.f;
#pragma unroll
        for (int w = 0; w < 8; w++) { ts += red[w]; tq += red[w + 8]; }
        float mu  = ts * (1.f / DM);
        float var = tq * (1.f / DM) - mu * mu;
        red[16] = mu;
        red[17] = rsqrtf(var + 1e-5f);
    }
    __syncthreads();
    float mu   = red[16];
    float rstd = red[17];

    float4 g = *(const float4*)(gamma + (tid << 2));
    float4 b = *(const float4*)(beta  + (tid << 2));
    float4 res;
    res.x = (v.x - mu) * rstd * g.x + b.x;
    res.y = (v.y - mu) * rstd * g.y + b.y;
    res.z = (v.z - mu) * rstd * g.z + b.z;
    res.w = (v.w - mu) * rstd * g.w + b.w;
    *(float4*)(out + (size_t)row * DM + (tid << 2)) = res;
}

// ---------------------------------------------------------------------------
// Launch
// ---------------------------------------------------------------------------
extern "C" void kernel_launch(void* const* d_in, const int* in_sizes, int n_in,
                              void* d_out, int out_size)
{
    const float*   x     = (const float*)d_in[0];
    const uint8_t* mask  = (const uint8_t*)d_in[1];
    const float*   wq    = (const float*)d_in[2];
    const float*   wk    = (const float*)d_in[3];
    const float*   wv    = (const float*)d_in[4];
    const float*   wo    = (const float*)d_in[5];
    const float*   gamma = (const float*)d_in[6];
    const float*   beta  = (const float*)d_in[7];
    float*         out   = (float*)d_out;

    const int attn_smem = (128 * 72 + 64 * 72 + 64 * 72 + 128 * 72) * 2; // 55296
    cudaFuncSetAttribute(attn_kernel,
                         cudaFuncAttributeMaxDynamicSharedMemorySize, attn_smem);

    mask_reduce_kernel<<<B_ * 16 * 32, 256>>>(mask);

    dim3 g1((B_ * L_) / 128, NH, 3);
    qkv_kernel<<<g1, 256>>>(x, wq, wk, wv);

    dim3 g2(L_ / 128, NH, B_);
    attn_kernel<<<g2, 128, attn_smem>>>(mask);

    dim3 g3((B_ * L_) / 128, DM / 64);
    oproj_kernel<<<g3, 256>>>(x, wo);

    ln_kernel<<<B_ * L_, 256>>>(gamma, beta, out);
}